// round 11
// baseline (speedup 1.0000x reference)
#include <cuda_runtime.h>
#include <cuda_bf16.h>
#include <math.h>
#include <stdint.h>

// ---------------- problem constants ----------------
#define BSZ 2
#define TSZ 1024
#define CSZ 768
#define LSZ 12
#define HSZ 12
#define HDSZ 64
#define VSZ 50257
#define BT (BSZ*TSZ)

// ---------------- device scratch (no allocation allowed) ----------------
__device__ float g_x  [BT*CSZ];      // residual stream
__device__ float g_h  [BT*CSZ];      // layernorm output
__device__ float g_qkv[BT*3*CSZ];    // qkv projection
__device__ float g_ao [BT*CSZ];      // attention output (pre-proj)
__device__ float g_hid[BT*4*CSZ];    // MLP hidden

// ---------------- reductions ----------------
__device__ __forceinline__ float warpReduceSum(float v){
    #pragma unroll
    for (int o = 16; o > 0; o >>= 1) v += __shfl_xor_sync(0xffffffffu, v, o);
    return v;
}
__device__ __forceinline__ float warpReduceMax(float v){
    #pragma unroll
    for (int o = 16; o > 0; o >>= 1) v = fmaxf(v, __shfl_xor_sync(0xffffffffu, v, o));
    return v;
}
__device__ __forceinline__ float blockReduceSum(float v, float* sh){
    int lane = threadIdx.x & 31, w = threadIdx.x >> 5;
    v = warpReduceSum(v);
    __syncthreads();
    if (lane == 0) sh[w] = v;
    __syncthreads();
    int nw = blockDim.x >> 5;
    float r = (threadIdx.x < nw) ? sh[threadIdx.x] : 0.0f;
    if (w == 0){ r = warpReduceSum(r); if (lane == 0) sh[0] = r; }
    __syncthreads();
    return sh[0];
}
__device__ __forceinline__ float blockReduceMax(float v, float* sh){
    int lane = threadIdx.x & 31, w = threadIdx.x >> 5;
    v = warpReduceMax(v);
    __syncthreads();
    if (lane == 0) sh[w] = v;
    __syncthreads();
    int nw = blockDim.x >> 5;
    float r = (threadIdx.x < nw) ? sh[threadIdx.x] : -1e30f;
    if (w == 0){ r = warpReduceMax(r); if (lane == 0) sh[0] = r; }
    __syncthreads();
    return sh[0];
}

// ---------------- embedding ----------------
__global__ void embed_kernel(const int* __restrict__ idx,
                             const float* __restrict__ wte,
                             const float* __restrict__ wpe,
                             float* __restrict__ x){
    int i = blockIdx.x * blockDim.x + threadIdx.x;
    if (i >= BT*CSZ) return;
    int c  = i % CSZ;
    int bt = i / CSZ;
    int t  = bt % TSZ;
    x[i] = wte[(size_t)idx[bt]*CSZ + c] + wpe[(size_t)t*CSZ + c];
}

// ---------------- layernorm ----------------
__global__ void __launch_bounds__(256) ln_kernel(const float* __restrict__ x,
                                                 const float* __restrict__ g,
                                                 const float* __restrict__ b,
                                                 float* __restrict__ out){
    __shared__ float sh[32];
    int row = blockIdx.x, tid = threadIdx.x;
    const float* xr = x + (size_t)row*CSZ;
    float v0 = xr[tid], v1 = xr[tid+256], v2 = xr[tid+512];
    float mean = blockReduceSum(v0+v1+v2, sh) * (1.0f/CSZ);
    float d0 = v0-mean, d1 = v1-mean, d2 = v2-mean;
    float var = blockReduceSum(d0*d0 + d1*d1 + d2*d2, sh) * (1.0f/CSZ);
    float rs = rsqrtf(var + 1e-5f);
    float* orow = out + (size_t)row*CSZ;
    orow[tid    ] = d0*rs*g[tid    ] + b[tid    ];
    orow[tid+256] = d1*rs*g[tid+256] + b[tid+256];
    orow[tid+512] = d2*rs*g[tid+512] + b[tid+512];
}

// =====================================================================
// bf16 split-precision tensor-core GEMM (hiA*hiB + hiA*loB + loA*hiB)
// C[M,N] = A[M,K] @ B (+bias +res, optional exact GELU)
// TRANSB=0: B is [K,N] row-major (N multiple of 128).
// TRANSB=1: B is [N,K] row-major (logits head; N guarded).
// M multiple of 128, K multiple of 32.
// =====================================================================
#define BM 128
#define BN 128
#define BK 32
#define APAD 8    // halves; A row stride 40 halves (80B) -> ldmatrix conflict-free
#define BPAD 8    // k-major B row stride 136 halves (272B) -> conflict-free

__device__ __forceinline__ void ldsm4(uint32_t* r, const __nv_bfloat16* p){
    uint32_t addr = (uint32_t)__cvta_generic_to_shared(p);
    asm volatile("ldmatrix.sync.aligned.m8n8.x4.shared.b16 {%0,%1,%2,%3}, [%4];"
        : "=r"(r[0]), "=r"(r[1]), "=r"(r[2]), "=r"(r[3]) : "r"(addr));
}
__device__ __forceinline__ void ldsm4t(uint32_t* r, const __nv_bfloat16* p){
    uint32_t addr = (uint32_t)__cvta_generic_to_shared(p);
    asm volatile("ldmatrix.sync.aligned.m8n8.x4.trans.shared.b16 {%0,%1,%2,%3}, [%4];"
        : "=r"(r[0]), "=r"(r[1]), "=r"(r[2]), "=r"(r[3]) : "r"(addr));
}
__device__ __forceinline__ void mma_bf16(float* c, const uint32_t* a, const uint32_t* b){
    asm volatile(
        "mma.sync.aligned.m16n8k16.row.col.f32.bf16.bf16.f32 "
        "{%0,%1,%2,%3}, {%4,%5,%6,%7}, {%8,%9}, {%0,%1,%2,%3};\n"
        : "+f"(c[0]), "+f"(c[1]), "+f"(c[2]), "+f"(c[3])
        : "r"(a[0]), "r"(a[1]), "r"(a[2]), "r"(a[3]), "r"(b[0]), "r"(b[1]));
}

// convert 8 floats (two float4) to hi/lo bf16 planes, 16B store each
__device__ __forceinline__ void cvt_store8(__nv_bfloat16* hip, __nv_bfloat16* lop,
                                           float4 v0, float4 v1){
    float f[8] = {v0.x, v0.y, v0.z, v0.w, v1.x, v1.y, v1.z, v1.w};
    uint32_t h[4], l[4];
    #pragma unroll
    for (int i = 0; i < 4; i++){
        float a = f[2*i], b = f[2*i+1];
        __nv_bfloat162 hb = __floats2bfloat162_rn(a, b);
        float2 hf = __bfloat1622float2(hb);
        __nv_bfloat162 lb = __floats2bfloat162_rn(a - hf.x, b - hf.y);
        h[i] = *(uint32_t*)&hb;
        l[i] = *(uint32_t*)&lb;
    }
    *(uint4*)hip = make_uint4(h[0], h[1], h[2], h[3]);
    *(uint4*)lop = make_uint4(l[0], l[1], l[2], l[3]);
}

template<int TRANSB>
__global__ void __launch_bounds__(256) gemm_kernel(
    const float* __restrict__ A, const float* __restrict__ B,
    const float* __restrict__ bias, const float* __restrict__ res,
    float* __restrict__ Cmat, int M, int N, int K, int doGelu)
{
    constexpr int ALD = BK + APAD;                    // 40 halves
    constexpr int BROWS = TRANSB ? BN : BK;
    constexpr int BLD   = TRANSB ? (BK + APAD) : (BN + BPAD);   // 40 or 136

    __shared__ __align__(16) __nv_bfloat16 As_hi[BM*ALD];
    __shared__ __align__(16) __nv_bfloat16 As_lo[BM*ALD];
    __shared__ __align__(16) __nv_bfloat16 Bs_hi[BROWS*BLD];
    __shared__ __align__(16) __nv_bfloat16 Bs_lo[BROWS*BLD];

    int tid = threadIdx.x;
    int lane = tid & 31, warp = tid >> 5;
    int bm = blockIdx.y * BM, bn = blockIdx.x * BN;
    int wm = (warp >> 2) * 64;      // warp grid: 2 (m) x 4 (n), warp tile 64x32
    int wn = (warp & 3) * 32;

    float acc[4][4][4];             // [mtile16][ntile8][frag]
    #pragma unroll
    for (int i = 0; i < 4; i++)
        #pragma unroll
        for (int j = 0; j < 4; j++)
            #pragma unroll
            for (int f = 0; f < 4; f++) acc[i][j][f] = 0.0f;

    // global-load assignments
    int arow = tid >> 1, akc = (tid & 1) * 16;        // A: 128 rows x 32 k
    const float* aptr = A + (size_t)(bm + arow)*K + akc;
    int bro, bco; const float* bptr; bool bvalid = true;
    if (!TRANSB){
        bro = tid >> 3; bco = (tid & 7) * 16;          // B: 32 k-rows x 128 n
        bptr = B + (size_t)bro*N + bn + bco;
    } else {
        bro = tid >> 1; bco = (tid & 1) * 16;          // B: 128 n-rows x 32 k
        int gn = bn + bro;
        bvalid = (gn < N);
        bptr = B + (size_t)gn*K + bco;
    }

    float4 pa[4], pb[4];
    // prologue: prefetch tile 0
    #pragma unroll
    for (int v = 0; v < 4; v++) pa[v] = *(const float4*)(aptr + v*4);
    #pragma unroll
    for (int v = 0; v < 4; v++)
        pb[v] = bvalid ? *(const float4*)(bptr + v*4) : make_float4(0,0,0,0);

    int ldgA = 0, ldgB = 0;  // offsets already consumed in pointers below via k0

    for (int k0 = 0; k0 < K; k0 += BK){
        // ---- convert + store current tile ----
        cvt_store8(&As_hi[arow*ALD + akc],     &As_lo[arow*ALD + akc],     pa[0], pa[1]);
        cvt_store8(&As_hi[arow*ALD + akc + 8], &As_lo[arow*ALD + akc + 8], pa[2], pa[3]);
        cvt_store8(&Bs_hi[bro*BLD + bco],      &Bs_lo[bro*BLD + bco],      pb[0], pb[1]);
        cvt_store8(&Bs_hi[bro*BLD + bco + 8],  &Bs_lo[bro*BLD + bco + 8],  pb[2], pb[3]);
        __syncthreads();

        // ---- prefetch next tile (LDGs overlap the MMA section) ----
        if (k0 + BK < K){
            const float* an = aptr + k0 + BK;
            #pragma unroll
            for (int v = 0; v < 4; v++) pa[v] = *(const float4*)(an + v*4);
            const float* bnp = bptr + (TRANSB ? (k0 + BK)
                                              : (size_t)(k0 + BK)*N);
            #pragma unroll
            for (int v = 0; v < 4; v++)
                pb[v] = bvalid ? *(const float4*)(bnp + v*4) : make_float4(0,0,0,0);
        }

        // ---- compute: 2 k-steps of 16 ----
        #pragma unroll
        for (int ks = 0; ks < 2; ks++){
            // B fragments: 4 n8-groups, hi & lo
            uint32_t bh[4][2], bl[4][2];
            #pragma unroll
            for (int j = 0; j < 2; j++){
                uint32_t r[4];
                if (!TRANSB){
                    int row = ks*16 + (lane & 15);
                    int col = wn + j*16 + (lane >> 4)*8;
                    ldsm4t(r, &Bs_hi[row*BLD + col]);
                    bh[2*j][0]=r[0]; bh[2*j][1]=r[1]; bh[2*j+1][0]=r[2]; bh[2*j+1][1]=r[3];
                    ldsm4t(r, &Bs_lo[row*BLD + col]);
                    bl[2*j][0]=r[0]; bl[2*j][1]=r[1]; bl[2*j+1][0]=r[2]; bl[2*j+1][1]=r[3];
                } else {
                    int row = wn + j*16 + (lane & 15);
                    int col = ks*16 + (lane >> 4)*8;
                    ldsm4(r, &Bs_hi[row*BLD + col]);
                    bh[2*j][0]=r[0]; bh[2*j][1]=r[2]; bh[2*j+1][0]=r[1]; bh[2*j+1][1]=r[3];
                    ldsm4(r, &Bs_lo[row*BLD + col]);
                    bl[2*j][0]=r[0]; bl[2*j][1]=r[2]; bl[2*j+1][0]=r[1]; bl[2*j+1][1]=r[3];
                }
            }
            // A fragments + MMAs
            #pragma unroll
            for (int mt = 0; mt < 4; mt++){
                int row = wm + mt*16 + (lane & 15);
                int col = ks*16 + (lane >> 4)*8;
                uint32_t ah[4], al[4];
                ldsm4(ah, &As_hi[row*ALD + col]);
                ldsm4(al, &As_lo[row*ALD + col]);
                #pragma unroll
                for (int nt = 0; nt < 4; nt++){
                    mma_bf16(acc[mt][nt], ah, bh[nt]);
                    mma_bf16(acc[mt][nt], ah, bl[nt]);
                    mma_bf16(acc[mt][nt], al, bh[nt]);
                }
            }
        }
        __syncthreads();
    }
    (void)ldgA; (void)ldgB;

    // ---- epilogue ----
    #pragma unroll
    for (int mt = 0; mt < 4; mt++){
        #pragma unroll
        for (int nt = 0; nt < 4; nt++){
            int row0 = bm + wm + mt*16 + (lane >> 2);
            int col0 = bn + wn + nt*8 + 2*(lane & 3);
            #pragma unroll
            for (int f = 0; f < 4; f++){
                int gm = row0 + ((f >= 2) ? 8 : 0);
                int gn = col0 + (f & 1);
                if (gn < N){
                    float v = acc[mt][nt][f];
                    if (bias) v += bias[gn];
                    if (res)  v += res[(size_t)gm*N + gn];
                    if (doGelu) v = 0.5f*v*(1.0f + erff(v*0.70710678118654752f));
                    Cmat[(size_t)gm*N + gn] = v;
                }
            }
        }
    }
}

// ---------------- fused causal attention: one block per (b,h,t) ----------------
__global__ void __launch_bounds__(128) attn_kernel(const float* __restrict__ qkv,
                                                   float* __restrict__ out){
    int t = blockIdx.x, h = blockIdx.y, b = blockIdx.z;
    __shared__ float q[HDSZ];
    __shared__ float p[TSZ];
    __shared__ float sh[32];
    int tid = threadIdx.x;

    const float* base = qkv + (size_t)b*TSZ*3*CSZ;
    const float* qr = base + (size_t)t*3*CSZ + h*3*HDSZ;
    if (tid < HDSZ) q[tid] = qr[tid] * 0.125f;   // 1/sqrt(64) folded into q
    __syncthreads();

    float mymax = -1e30f;
    for (int s = tid; s <= t; s += 128){
        const float* kr = base + (size_t)s*3*CSZ + h*3*HDSZ + HDSZ;
        float d = 0.0f;
        #pragma unroll
        for (int i = 0; i < HDSZ; i++) d = fmaf(q[i], kr[i], d);
        p[s] = d;
        mymax = fmaxf(mymax, d);
    }
    float mx = blockReduceMax(mymax, sh);

    float mysum = 0.0f;
    for (int s = tid; s <= t; s += 128){
        float e = __expf(p[s] - mx);
        p[s] = e;
        mysum += e;
    }
    float inv = 1.0f / blockReduceSum(mysum, sh);

    if (tid < HDSZ){
        float acc = 0.0f;
        const float* vr = base + h*3*HDSZ + 2*HDSZ + tid;
        for (int s = 0; s <= t; s++)
            acc = fmaf(p[s], vr[(size_t)s*3*CSZ], acc);
        out[((size_t)(b*TSZ + t))*CSZ + h*HDSZ + tid] = acc * inv;
    }
}

// ---------------- launch ----------------
extern "C" void kernel_launch(void* const* d_in, const int* in_sizes, int n_in,
                              void* d_out, int out_size)
{
    const int*   idx    = (const int*)  d_in[0];
    const float* wte    = (const float*)d_in[1];
    const float* wpe    = (const float*)d_in[2];
    const float* ln1_g  = (const float*)d_in[3];
    const float* ln1_b  = (const float*)d_in[4];
    const float* attn_w = (const float*)d_in[5];
    const float* attn_b = (const float*)d_in[6];
    const float* proj_w = (const float*)d_in[7];
    const float* proj_b = (const float*)d_in[8];
    const float* ln2_g  = (const float*)d_in[9];
    const float* ln2_b  = (const float*)d_in[10];
    const float* fc_w   = (const float*)d_in[11];
    const float* fc_b   = (const float*)d_in[12];
    const float* fp_w   = (const float*)d_in[13];
    const float* fp_b   = (const float*)d_in[14];
    const float* lnf_g  = (const float*)d_in[15];
    const float* lnf_b  = (const float*)d_in[16];
    float* out = (float*)d_out;

    float *x, *h, *qkv, *ao, *hid;
    cudaGetSymbolAddress((void**)&x,   g_x);
    cudaGetSymbolAddress((void**)&h,   g_h);
    cudaGetSymbolAddress((void**)&qkv, g_qkv);
    cudaGetSymbolAddress((void**)&ao,  g_ao);
    cudaGetSymbolAddress((void**)&hid, g_hid);

    embed_kernel<<<(BT*CSZ + 255)/256, 256>>>(idx, wte, wpe, x);

    for (int l = 0; l < LSZ; l++){
        // attention
        ln_kernel<<<BT, 256>>>(x, ln1_g + (size_t)l*CSZ, ln1_b + (size_t)l*CSZ, h);
        gemm_kernel<0><<<dim3(3*CSZ/BN, BT/BM), 256>>>(
            h, attn_w + (size_t)l*CSZ*3*CSZ, attn_b + (size_t)l*3*CSZ,
            nullptr, qkv, BT, 3*CSZ, CSZ, 0);
        attn_kernel<<<dim3(TSZ, HSZ, BSZ), 128>>>(qkv, ao);
        gemm_kernel<0><<<dim3(CSZ/BN, BT/BM), 256>>>(
            ao, proj_w + (size_t)l*CSZ*CSZ, proj_b + (size_t)l*CSZ,
            x, x, BT, CSZ, CSZ, 0);
        // MLP
        ln_kernel<<<BT, 256>>>(x, ln2_g + (size_t)l*CSZ, ln2_b + (size_t)l*CSZ, h);
        gemm_kernel<0><<<dim3(4*CSZ/BN, BT/BM), 256>>>(
            h, fc_w + (size_t)l*CSZ*4*CSZ, fc_b + (size_t)l*4*CSZ,
            nullptr, hid, BT, 4*CSZ, CSZ, 1);
        gemm_kernel<0><<<dim3(CSZ/BN, BT/BM), 256>>>(
            hid, fp_w + (size_t)l*4*CSZ*CSZ, fp_b + (size_t)l*CSZ,
            x, x, BT, CSZ, 4*CSZ, 0);
    }

    // final LN + tied-embedding logits head (wte is [V, C] = [N, K])
    ln_kernel<<<BT, 256>>>(x, lnf_g, lnf_b, h);
    gemm_kernel<1><<<dim3((VSZ + BN - 1)/BN, BT/BM), 256>>>(
        h, wte, nullptr, nullptr, out, BT, VSZ, CSZ, 0);
}

// round 12
// speedup vs baseline: 1.0011x; 1.0011x over previous
#include <cuda_runtime.h>
#include <cuda_bf16.h>
#include <math.h>
#include <stdint.h>

// ---------------- problem constants ----------------
#define BSZ 2
#define TSZ 1024
#define CSZ 768
#define LSZ 12
#define HSZ 12
#define HDSZ 64
#define VSZ 50257
#define BT (BSZ*TSZ)

// ---------------- device scratch (no allocation allowed) ----------------
__device__ float g_x  [BT*CSZ];      // residual stream
__device__ float g_h  [BT*CSZ];      // layernorm output
__device__ float g_qkv[BT*3*CSZ];    // qkv projection
__device__ float g_ao [BT*CSZ];      // attention output (pre-proj)
__device__ float g_hid[BT*4*CSZ];    // MLP hidden

// ---------------- reductions ----------------
__device__ __forceinline__ float warpReduceSum(float v){
    #pragma unroll
    for (int o = 16; o > 0; o >>= 1) v += __shfl_xor_sync(0xffffffffu, v, o);
    return v;
}
__device__ __forceinline__ float warpReduceMax(float v){
    #pragma unroll
    for (int o = 16; o > 0; o >>= 1) v = fmaxf(v, __shfl_xor_sync(0xffffffffu, v, o));
    return v;
}
__device__ __forceinline__ float blockReduceSum(float v, float* sh){
    int lane = threadIdx.x & 31, w = threadIdx.x >> 5;
    v = warpReduceSum(v);
    __syncthreads();
    if (lane == 0) sh[w] = v;
    __syncthreads();
    int nw = blockDim.x >> 5;
    float r = (threadIdx.x < nw) ? sh[threadIdx.x] : 0.0f;
    if (w == 0){ r = warpReduceSum(r); if (lane == 0) sh[0] = r; }
    __syncthreads();
    return sh[0];
}
__device__ __forceinline__ float blockReduceMax(float v, float* sh){
    int lane = threadIdx.x & 31, w = threadIdx.x >> 5;
    v = warpReduceMax(v);
    __syncthreads();
    if (lane == 0) sh[w] = v;
    __syncthreads();
    int nw = blockDim.x >> 5;
    float r = (threadIdx.x < nw) ? sh[threadIdx.x] : -1e30f;
    if (w == 0){ r = warpReduceMax(r); if (lane == 0) sh[0] = r; }
    __syncthreads();
    return sh[0];
}

// ---------------- embedding ----------------
__global__ void embed_kernel(const int* __restrict__ idx,
                             const float* __restrict__ wte,
                             const float* __restrict__ wpe,
                             float* __restrict__ x){
    int i = blockIdx.x * blockDim.x + threadIdx.x;
    if (i >= BT*CSZ) return;
    int c  = i % CSZ;
    int bt = i / CSZ;
    int t  = bt % TSZ;
    x[i] = wte[(size_t)idx[bt]*CSZ + c] + wpe[(size_t)t*CSZ + c];
}

// ---------------- layernorm ----------------
__global__ void __launch_bounds__(256) ln_kernel(const float* __restrict__ x,
                                                 const float* __restrict__ g,
                                                 const float* __restrict__ b,
                                                 float* __restrict__ out){
    __shared__ float sh[32];
    int row = blockIdx.x, tid = threadIdx.x;
    const float* xr = x + (size_t)row*CSZ;
    float v0 = xr[tid], v1 = xr[tid+256], v2 = xr[tid+512];
    float mean = blockReduceSum(v0+v1+v2, sh) * (1.0f/CSZ);
    float d0 = v0-mean, d1 = v1-mean, d2 = v2-mean;
    float var = blockReduceSum(d0*d0 + d1*d1 + d2*d2, sh) * (1.0f/CSZ);
    float rs = rsqrtf(var + 1e-5f);
    float* orow = out + (size_t)row*CSZ;
    orow[tid    ] = d0*rs*g[tid    ] + b[tid    ];
    orow[tid+256] = d1*rs*g[tid+256] + b[tid+256];
    orow[tid+512] = d2*rs*g[tid+512] + b[tid+512];
}

// =====================================================================
// bf16 split-precision tensor-core GEMM (hiA*hiB + hiA*loB + loA*hiB)
// C[M,N] = A[M,K] @ B (+bias +res, optional exact GELU)
// TRANSB=0: B is [K,N] row-major (N multiple of 128).
// TRANSB=1: B is [N,K] row-major (logits head; N guarded).
// M multiple of 128, K multiple of 32.
// =====================================================================
#define BM 128
#define BN 128
#define BK 32
#define APAD 8    // halves; A row stride 40 halves (80B) -> ldmatrix conflict-free
#define BPAD 8    // k-major B row stride 136 halves (272B) -> conflict-free

__device__ __forceinline__ void ldsm4(uint32_t* r, const __nv_bfloat16* p){
    uint32_t addr = (uint32_t)__cvta_generic_to_shared(p);
    asm volatile("ldmatrix.sync.aligned.m8n8.x4.shared.b16 {%0,%1,%2,%3}, [%4];"
        : "=r"(r[0]), "=r"(r[1]), "=r"(r[2]), "=r"(r[3]) : "r"(addr));
}
__device__ __forceinline__ void ldsm4t(uint32_t* r, const __nv_bfloat16* p){
    uint32_t addr = (uint32_t)__cvta_generic_to_shared(p);
    asm volatile("ldmatrix.sync.aligned.m8n8.x4.trans.shared.b16 {%0,%1,%2,%3}, [%4];"
        : "=r"(r[0]), "=r"(r[1]), "=r"(r[2]), "=r"(r[3]) : "r"(addr));
}
__device__ __forceinline__ void mma_bf16(float* c, const uint32_t* a, const uint32_t* b){
    asm volatile(
        "mma.sync.aligned.m16n8k16.row.col.f32.bf16.bf16.f32 "
        "{%0,%1,%2,%3}, {%4,%5,%6,%7}, {%8,%9}, {%0,%1,%2,%3};\n"
        : "+f"(c[0]), "+f"(c[1]), "+f"(c[2]), "+f"(c[3])
        : "r"(a[0]), "r"(a[1]), "r"(a[2]), "r"(a[3]), "r"(b[0]), "r"(b[1]));
}

// convert 8 floats (two float4) to hi/lo bf16 planes, 16B store each
__device__ __forceinline__ void cvt_store8(__nv_bfloat16* hip, __nv_bfloat16* lop,
                                           float4 v0, float4 v1){
    float f[8] = {v0.x, v0.y, v0.z, v0.w, v1.x, v1.y, v1.z, v1.w};
    uint32_t h[4], l[4];
    #pragma unroll
    for (int i = 0; i < 4; i++){
        float a = f[2*i], b = f[2*i+1];
        __nv_bfloat162 hb = __floats2bfloat162_rn(a, b);
        float2 hf = __bfloat1622float2(hb);
        __nv_bfloat162 lb = __floats2bfloat162_rn(a - hf.x, b - hf.y);
        h[i] = *(uint32_t*)&hb;
        l[i] = *(uint32_t*)&lb;
    }
    *(uint4*)hip = make_uint4(h[0], h[1], h[2], h[3]);
    *(uint4*)lop = make_uint4(l[0], l[1], l[2], l[3]);
}

template<int TRANSB>
__global__ void __launch_bounds__(256) gemm_kernel(
    const float* __restrict__ A, const float* __restrict__ B,
    const float* __restrict__ bias, const float* __restrict__ res,
    float* __restrict__ Cmat, int M, int N, int K, int doGelu)
{
    constexpr int ALD = BK + APAD;                    // 40 halves
    constexpr int BROWS = TRANSB ? BN : BK;
    constexpr int BLD   = TRANSB ? (BK + APAD) : (BN + BPAD);   // 40 or 136

    __shared__ __align__(16) __nv_bfloat16 As_hi[BM*ALD];
    __shared__ __align__(16) __nv_bfloat16 As_lo[BM*ALD];
    __shared__ __align__(16) __nv_bfloat16 Bs_hi[BROWS*BLD];
    __shared__ __align__(16) __nv_bfloat16 Bs_lo[BROWS*BLD];

    int tid = threadIdx.x;
    int lane = tid & 31, warp = tid >> 5;
    int bm = blockIdx.y * BM, bn = blockIdx.x * BN;
    int wm = (warp >> 2) * 64;      // warp grid: 2 (m) x 4 (n), warp tile 64x32
    int wn = (warp & 3) * 32;

    float acc[4][4][4];             // [mtile16][ntile8][frag]
    #pragma unroll
    for (int i = 0; i < 4; i++)
        #pragma unroll
        for (int j = 0; j < 4; j++)
            #pragma unroll
            for (int f = 0; f < 4; f++) acc[i][j][f] = 0.0f;

    // global-load assignments
    int arow = tid >> 1, akc = (tid & 1) * 16;        // A: 128 rows x 32 k
    const float* aptr = A + (size_t)(bm + arow)*K + akc;
    int bro, bco; const float* bptr; bool bvalid = true;
    if (!TRANSB){
        bro = tid >> 3; bco = (tid & 7) * 16;          // B: 32 k-rows x 128 n
        bptr = B + (size_t)bro*N + bn + bco;
    } else {
        bro = tid >> 1; bco = (tid & 1) * 16;          // B: 128 n-rows x 32 k
        int gn = bn + bro;
        bvalid = (gn < N);
        bptr = B + (size_t)gn*K + bco;
    }

    float4 pa[4], pb[4];
    // prologue: prefetch tile 0
    #pragma unroll
    for (int v = 0; v < 4; v++) pa[v] = *(const float4*)(aptr + v*4);
    #pragma unroll
    for (int v = 0; v < 4; v++)
        pb[v] = bvalid ? *(const float4*)(bptr + v*4) : make_float4(0,0,0,0);

    int ldgA = 0, ldgB = 0;  // offsets already consumed in pointers below via k0

    for (int k0 = 0; k0 < K; k0 += BK){
        // ---- convert + store current tile ----
        cvt_store8(&As_hi[arow*ALD + akc],     &As_lo[arow*ALD + akc],     pa[0], pa[1]);
        cvt_store8(&As_hi[arow*ALD + akc + 8], &As_lo[arow*ALD + akc + 8], pa[2], pa[3]);
        cvt_store8(&Bs_hi[bro*BLD + bco],      &Bs_lo[bro*BLD + bco],      pb[0], pb[1]);
        cvt_store8(&Bs_hi[bro*BLD + bco + 8],  &Bs_lo[bro*BLD + bco + 8],  pb[2], pb[3]);
        __syncthreads();

        // ---- prefetch next tile (LDGs overlap the MMA section) ----
        if (k0 + BK < K){
            const float* an = aptr + k0 + BK;
            #pragma unroll
            for (int v = 0; v < 4; v++) pa[v] = *(const float4*)(an + v*4);
            const float* bnp = bptr + (TRANSB ? (k0 + BK)
                                              : (size_t)(k0 + BK)*N);
            #pragma unroll
            for (int v = 0; v < 4; v++)
                pb[v] = bvalid ? *(const float4*)(bnp + v*4) : make_float4(0,0,0,0);
        }

        // ---- compute: 2 k-steps of 16 ----
        #pragma unroll
        for (int ks = 0; ks < 2; ks++){
            // B fragments: 4 n8-groups, hi & lo
            uint32_t bh[4][2], bl[4][2];
            #pragma unroll
            for (int j = 0; j < 2; j++){
                uint32_t r[4];
                if (!TRANSB){
                    int row = ks*16 + (lane & 15);
                    int col = wn + j*16 + (lane >> 4)*8;
                    ldsm4t(r, &Bs_hi[row*BLD + col]);
                    bh[2*j][0]=r[0]; bh[2*j][1]=r[1]; bh[2*j+1][0]=r[2]; bh[2*j+1][1]=r[3];
                    ldsm4t(r, &Bs_lo[row*BLD + col]);
                    bl[2*j][0]=r[0]; bl[2*j][1]=r[1]; bl[2*j+1][0]=r[2]; bl[2*j+1][1]=r[3];
                } else {
                    int row = wn + j*16 + (lane & 15);
                    int col = ks*16 + (lane >> 4)*8;
                    ldsm4(r, &Bs_hi[row*BLD + col]);
                    bh[2*j][0]=r[0]; bh[2*j][1]=r[2]; bh[2*j+1][0]=r[1]; bh[2*j+1][1]=r[3];
                    ldsm4(r, &Bs_lo[row*BLD + col]);
                    bl[2*j][0]=r[0]; bl[2*j][1]=r[2]; bl[2*j+1][0]=r[1]; bl[2*j+1][1]=r[3];
                }
            }
            // A fragments + MMAs
            #pragma unroll
            for (int mt = 0; mt < 4; mt++){
                int row = wm + mt*16 + (lane & 15);
                int col = ks*16 + (lane >> 4)*8;
                uint32_t ah[4], al[4];
                ldsm4(ah, &As_hi[row*ALD + col]);
                ldsm4(al, &As_lo[row*ALD + col]);
                #pragma unroll
                for (int nt = 0; nt < 4; nt++){
                    mma_bf16(acc[mt][nt], ah, bh[nt]);
                    mma_bf16(acc[mt][nt], ah, bl[nt]);
                    mma_bf16(acc[mt][nt], al, bh[nt]);
                }
            }
        }
        __syncthreads();
    }
    (void)ldgA; (void)ldgB;

    // ---- epilogue ----
    #pragma unroll
    for (int mt = 0; mt < 4; mt++){
        #pragma unroll
        for (int nt = 0; nt < 4; nt++){
            int row0 = bm + wm + mt*16 + (lane >> 2);
            int col0 = bn + wn + nt*8 + 2*(lane & 3);
            #pragma unroll
            for (int f = 0; f < 4; f++){
                int gm = row0 + ((f >= 2) ? 8 : 0);
                int gn = col0 + (f & 1);
                if (gn < N){
                    float v = acc[mt][nt][f];
                    if (bias) v += bias[gn];
                    if (res)  v += res[(size_t)gm*N + gn];
                    if (doGelu) v = 0.5f*v*(1.0f + erff(v*0.70710678118654752f));
                    Cmat[(size_t)gm*N + gn] = v;
                }
            }
        }
    }
}

// ---------------- fused causal attention: one block per (b,h,t) ----------------
__global__ void __launch_bounds__(128) attn_kernel(const float* __restrict__ qkv,
                                                   float* __restrict__ out){
    int t = blockIdx.x, h = blockIdx.y, b = blockIdx.z;
    __shared__ float q[HDSZ];
    __shared__ float p[TSZ];
    __shared__ float sh[32];
    int tid = threadIdx.x;

    const float* base = qkv + (size_t)b*TSZ*3*CSZ;
    const float* qr = base + (size_t)t*3*CSZ + h*3*HDSZ;
    if (tid < HDSZ) q[tid] = qr[tid] * 0.125f;   // 1/sqrt(64) folded into q
    __syncthreads();

    float mymax = -1e30f;
    for (int s = tid; s <= t; s += 128){
        const float* kr = base + (size_t)s*3*CSZ + h*3*HDSZ + HDSZ;
        float d = 0.0f;
        #pragma unroll
        for (int i = 0; i < HDSZ; i++) d = fmaf(q[i], kr[i], d);
        p[s] = d;
        mymax = fmaxf(mymax, d);
    }
    float mx = blockReduceMax(mymax, sh);

    float mysum = 0.0f;
    for (int s = tid; s <= t; s += 128){
        float e = __expf(p[s] - mx);
        p[s] = e;
        mysum += e;
    }
    float inv = 1.0f / blockReduceSum(mysum, sh);

    if (tid < HDSZ){
        float acc = 0.0f;
        const float* vr = base + h*3*HDSZ + 2*HDSZ + tid;
        for (int s = 0; s <= t; s++)
            acc = fmaf(p[s], vr[(size_t)s*3*CSZ], acc);
        out[((size_t)(b*TSZ + t))*CSZ + h*HDSZ + tid] = acc * inv;
    }
}

// ---------------- launch ----------------
extern "C" void kernel_launch(void* const* d_in, const int* in_sizes, int n_in,
                              void* d_out, int out_size)
{
    const int*   idx    = (const int*)  d_in[0];
    const float* wte    = (const float*)d_in[1];
    const float* wpe    = (const float*)d_in[2];
    const float* ln1_g  = (const float*)d_in[3];
    const float* ln1_b  = (const float*)d_in[4];
    const float* attn_w = (const float*)d_in[5];
    const float* attn_b = (const float*)d_in[6];
    const float* proj_w = (const float*)d_in[7];
    const float* proj_b = (const float*)d_in[8];
    const float* ln2_g  = (const float*)d_in[9];
    const float* ln2_b  = (const float*)d_in[10];
    const float* fc_w   = (const float*)d_in[11];
    const float* fc_b   = (const float*)d_in[12];
    const float* fp_w   = (const float*)d_in[13];
    const float* fp_b   = (const float*)d_in[14];
    const float* lnf_g  = (const float*)d_in[15];
    const float* lnf_b  = (const float*)d_in[16];
    float* out = (float*)d_out;

    float *x, *h, *qkv, *ao, *hid;
    cudaGetSymbolAddress((void**)&x,   g_x);
    cudaGetSymbolAddress((void**)&h,   g_h);
    cudaGetSymbolAddress((void**)&qkv, g_qkv);
    cudaGetSymbolAddress((void**)&ao,  g_ao);
    cudaGetSymbolAddress((void**)&hid, g_hid);

    embed_kernel<<<(BT*CSZ + 255)/256, 256>>>(idx, wte, wpe, x);

    for (int l = 0; l < LSZ; l++){
        // attention
        ln_kernel<<<BT, 256>>>(x, ln1_g + (size_t)l*CSZ, ln1_b + (size_t)l*CSZ, h);
        gemm_kernel<0><<<dim3(3*CSZ/BN, BT/BM), 256>>>(
            h, attn_w + (size_t)l*CSZ*3*CSZ, attn_b + (size_t)l*3*CSZ,
            nullptr, qkv, BT, 3*CSZ, CSZ, 0);
        attn_kernel<<<dim3(TSZ, HSZ, BSZ), 128>>>(qkv, ao);
        gemm_kernel<0><<<dim3(CSZ/BN, BT/BM), 256>>>(
            ao, proj_w + (size_t)l*CSZ*CSZ, proj_b + (size_t)l*CSZ,
            x, x, BT, CSZ, CSZ, 0);
        // MLP
        ln_kernel<<<BT, 256>>>(x, ln2_g + (size_t)l*CSZ, ln2_b + (size_t)l*CSZ, h);
        gemm_kernel<0><<<dim3(4*CSZ/BN, BT/BM), 256>>>(
            h, fc_w + (size_t)l*CSZ*4*CSZ, fc_b + (size_t)l*4*CSZ,
            nullptr, hid, BT, 4*CSZ, CSZ, 1);
        gemm_kernel<0><<<dim3(CSZ/BN, BT/BM), 256>>>(
            hid, fp_w + (size_t)l*4*CSZ*CSZ, fp_b + (size_t)l*CSZ,
            x, x, BT, CSZ, 4*CSZ, 0);
    }

    // final LN + tied-embedding logits head (wte is [V, C] = [N, K])
    ln_kernel<<<BT, 256>>>(x, lnf_g, lnf_b, h);
    gemm_kernel<1><<<dim3((VSZ + BN - 1)/BN, BT/BM), 256>>>(
        h, wte, nullptr, nullptr, out, BT, VSZ, CSZ, 0);
}